// round 3
// baseline (speedup 1.0000x reference)
#include <cuda_runtime.h>

// Depthwise cross-correlation (XLA conv semantics, no kernel flip):
//   out[ch, ho, wo] = sum_{ky<7, kx<7} x[ch, ho+ky, wo+kx] * z[ch, ky, kx]
// x: [32768, 31, 31], z: [32768, 7, 7], out: [32768, 25, 25], all fp32.

#define HX 31
#define WX 31
#define HZ 7
#define WZ 7
#define HO 25
#define WO 25
#define XPAD 32                      // padded x row stride (floats)
#define GRP 5                        // channels per 128-thread CTA
#define NCH (128 * 256)
#define CH_STRIDE_X (HX * XPAD + 16) // 1008 floats: +16 breaks bank aliasing mod 32

__device__ __forceinline__ void fma2(unsigned long long &d,
                                     unsigned long long a,
                                     unsigned long long b) {
    // packed f32x2 FMA (sm_100+): d.lo += a.lo*b.lo; d.hi += a.hi*b.hi
    asm("fma.rn.f32x2 %0, %1, %2, %0;" : "+l"(d) : "l"(a), "l"(b));
}

__global__ void __launch_bounds__(128, 4)
dwxcorr_f32x2_g5(const float* __restrict__ zf,
                 const float* __restrict__ xf,
                 float* __restrict__ out) {
    __shared__ float sx[GRP * CH_STRIDE_X];
    __shared__ float sk[GRP][2][HZ][8];     // [parity][ky][padded taps]

    const int tid  = threadIdx.x;
    const int base = blockIdx.x * GRP;
    const int nch  = min(GRP, NCH - base);

    // ---- stage x tiles (all 128 threads cooperate) ----
    for (int i = tid; i < nch * HX * WX; i += 128) {
        int g   = i / (HX * WX);
        int rem = i - g * (HX * WX);
        int r   = rem / WX;
        int c   = rem - r * WX;
        sx[g * CH_STRIDE_X + r * XPAD + c] =
            xf[(long long)(base + g) * (HX * WX) + rem];
    }
    // zero the pad column (col 31) for all groups
    for (int i = tid; i < GRP * HX; i += 128) {
        int g = i / HX;
        int r = i - g * HX;
        sx[g * CH_STRIDE_X + r * XPAD + WX] = 0.0f;
    }

    // ---- stage kernels: two parity-shifted zero-padded copies ----
    // even copy: [k0 k1 k2 k3 k4 k5 k6 0]
    // odd  copy: [0  k0 k1 k2 k3 k4 k5 k6]
    for (int i = tid; i < nch * HZ * 8; i += 128) {
        int g   = i / (HZ * 8);
        int rem = i - g * (HZ * 8);
        int ky  = rem >> 3;
        int j   = rem & 7;
        const float* zc = zf + (long long)(base + g) * (HZ * WZ);
        sk[g][0][ky][j] = (j < WZ)  ? zc[ky * WZ + j]       : 0.0f;
        sk[g][1][ky][j] = (j >= 1)  ? zc[ky * WZ + (j - 1)] : 0.0f;
    }
    __syncthreads();

    // ---- compute: 25 threads per channel, one output column each ----
    const int g  = tid / WO;         // channel group 0..4
    const int wo = tid - g * WO;     // output column 0..24
    if (tid >= GRP * WO || g >= nch) return;

    const int par = wo & 1;
    const int x0  = wo & ~1;         // even-aligned pair base
    const float* __restrict__ sxg = &sx[g * CH_STRIDE_X + x0];

    // kernel tap pairs for this parity -> registers (28 x f32x2)
    unsigned long long kk[HZ][4];
#pragma unroll
    for (int ky = 0; ky < HZ; ky++) {
#pragma unroll
        for (int j = 0; j < 4; j++) {
            kk[ky][j] = *reinterpret_cast<const unsigned long long*>(
                &sk[g][par][ky][2 * j]);
        }
    }

    unsigned long long acc[HO];      // f32x2 accumulators, one per output row
#pragma unroll
    for (int i = 0; i < HO; i++) acc[i] = 0ULL;

    // software-pipelined walk over the 31 x rows; each row feeds <=7 out rows
    unsigned long long p0 = *reinterpret_cast<const unsigned long long*>(sxg + 0);
    unsigned long long p1 = *reinterpret_cast<const unsigned long long*>(sxg + 2);
    unsigned long long p2 = *reinterpret_cast<const unsigned long long*>(sxg + 4);
    unsigned long long p3 = *reinterpret_cast<const unsigned long long*>(sxg + 6);

#pragma unroll
    for (int r = 0; r < HX; r++) {
        unsigned long long q0 = 0, q1 = 0, q2 = 0, q3 = 0;
        if (r < HX - 1) {
            const float* nx = sxg + (r + 1) * XPAD;
            q0 = *reinterpret_cast<const unsigned long long*>(nx + 0);
            q1 = *reinterpret_cast<const unsigned long long*>(nx + 2);
            q2 = *reinterpret_cast<const unsigned long long*>(nx + 4);
            q3 = *reinterpret_cast<const unsigned long long*>(nx + 6);
        }
#pragma unroll
        for (int ky = 0; ky < HZ; ky++) {
            const int ho = r - ky;
            if (ho >= 0 && ho < HO) {
                fma2(acc[ho], p0, kk[ky][0]);
                fma2(acc[ho], p1, kk[ky][1]);
                fma2(acc[ho], p2, kk[ky][2]);
                fma2(acc[ho], p3, kk[ky][3]);
            }
        }
        p0 = q0; p1 = q1; p2 = q2; p3 = q3;
    }

    float* __restrict__ och = out + (long long)(base + g) * (HO * WO) + wo;
#pragma unroll
    for (int ho = 0; ho < HO; ho++) {
        float2 v = *reinterpret_cast<float2*>(&acc[ho]);
        och[ho * WO] = v.x + v.y;
    }
}

extern "C" void kernel_launch(void* const* d_in, const int* in_sizes, int n_in,
                              void* d_out, int out_size) {
    // metadata order: z_f [128,256,7,7] then x_f [128,256,31,31]
    const float* z = (const float*)d_in[0];
    const float* x = (const float*)d_in[1];
    if (n_in >= 2 && in_sizes[0] > in_sizes[1]) {   // defensive: z is the small one
        const float* t = z; z = x; x = t;
    }
    float* o = (float*)d_out;

    dim3 grid((NCH + GRP - 1) / GRP);
    dim3 block(128);
    dwxcorr_f32x2_g5<<<grid, block>>>(z, x, o);
}